// round 7
// baseline (speedup 1.0000x reference)
#include <cuda_runtime.h>

#define BB 8192
#define FF 32
#define EE 64
#define PP 496   // 32 choose 2

template<int P0>
__device__ __forceinline__ void store_group(const float (&xwc)[FF],
                                            const float (&xc)[FF],
                                            float* __restrict__ outb)
{
    #pragma unroll
    for (int i = 0; i < FF - 1; i++) {
        #pragma unroll
        for (int j = i + 1; j < FF; j++) {
            const int p = i * (2 * FF - 1 - i) / 2 + (j - i - 1); // i*(63-i)/2 + ...
            if (p >= P0 && p < P0 + PP / 4) {
                // streaming scalar store: 32 consecutive d-lanes -> 128B coalesced
                __stcs(outb + p * EE, xwc[i] * xc[j]);
            }
        }
    }
}

__global__ __launch_bounds__(256, 3)
void bilinear_pair_kernel(const float* __restrict__ x,
                          const float* __restrict__ W,
                          float* __restrict__ out)
{
    __shared__ float Ws[EE * EE];    // 16 KB  W[e*64+d]
    __shared__ float xs[FF * EE];    // 8 KB   x[b][f*64+e]
    __shared__ float xws[FF * EE];   // 8 KB   (x[b] @ W)

    const int b   = blockIdx.x;
    const int tid = threadIdx.x;

    // ---- load W (4096 floats) and x[b] (2048 floats) as float4 ----
    {
        const float4* W4  = (const float4*)W;
        float4*       Ws4 = (float4*)Ws;
        #pragma unroll
        for (int k = tid; k < EE * EE / 4; k += 256)
            Ws4[k] = W4[k];

        const float4* x4  = (const float4*)(x + (size_t)b * FF * EE);
        float4*       xs4 = (float4*)xs;
        #pragma unroll
        for (int k = tid; k < FF * EE / 4; k += 256)
            xs4[k] = x4[k];
    }
    __syncthreads();

    // ---- matmul: thread = 2 rows x 4 cols register tile ----
    // per e: 2 broadcast scalar LDS + 1 conflict-free LDS.128, 8 FMA
    {
        const int r0 = (tid >> 4) * 2;       // rows r0, r0+1
        const int c4 = (tid & 15) * 4;       // cols c4..c4+3
        float4 acc0 = make_float4(0.f, 0.f, 0.f, 0.f);
        float4 acc1 = make_float4(0.f, 0.f, 0.f, 0.f);

        #pragma unroll 16
        for (int e = 0; e < EE; e++) {
            float4 w = *(const float4*)(Ws + e * EE + c4);
            float  a0 = xs[r0 * EE + e];
            float  a1 = xs[(r0 + 1) * EE + e];
            acc0.x = fmaf(a0, w.x, acc0.x);
            acc0.y = fmaf(a0, w.y, acc0.y);
            acc0.z = fmaf(a0, w.z, acc0.z);
            acc0.w = fmaf(a0, w.w, acc0.w);
            acc1.x = fmaf(a1, w.x, acc1.x);
            acc1.y = fmaf(a1, w.y, acc1.y);
            acc1.z = fmaf(a1, w.z, acc1.z);
            acc1.w = fmaf(a1, w.w, acc1.w);
        }
        *(float4*)(xws + r0 * EE + c4)       = acc0;
        *(float4*)(xws + (r0 + 1) * EE + c4) = acc1;
    }
    __syncthreads();

    // ---- register-cache this thread's e-column of xs and xws ----
    // thread owns column d = tid & 63; group g = tid >> 6 owns 124 pairs.
    // Consecutive lanes -> consecutive d -> conflict-free LDS / coalesced STG.
    {
        const int d = tid & 63;
        const int g = tid >> 6;

        float xc[FF];
        float xwc[FF];
        #pragma unroll
        for (int f = 0; f < FF; f++) {
            xc[f]  = xs[f * EE + d];
            xwc[f] = xws[f * EE + d];
        }

        float* outb = out + (size_t)b * PP * EE + d;

        // hot loop: pure registers -> 1 FMUL + 1 STG.32.cs per pair, zero LDS
        switch (g) {
            case 0: store_group<0>(xwc, xc, outb); break;
            case 1: store_group<124>(xwc, xc, outb); break;
            case 2: store_group<248>(xwc, xc, outb); break;
            default: store_group<372>(xwc, xc, outb); break;
        }
    }
}

extern "C" void kernel_launch(void* const* d_in, const int* in_sizes, int n_in,
                              void* d_out, int out_size)
{
    const float* x = (const float*)d_in[0];
    const float* W = (const float*)d_in[1];
    float*       o = (float*)d_out;
    bilinear_pair_kernel<<<BB, 256>>>(x, W, o);
}